// round 11
// baseline (speedup 1.0000x reference)
#include <cuda_runtime.h>
#include <cuda_fp16.h>
#include <math.h>
#include <stdint.h>

// ---------------- problem constants -----------------------------------------
#define NTOK 4096
#define HD   1024
#define NE   8
#define FD   4096
#define NSLOT (NTOK * 2)
#define NSLOTP (NSLOT + NE * 128)      // 128-padded per-expert ranges
#define MAXMT 71                        // max total m-tiles (64 + 7 pad)

// ---------------- GEMM tiling: 128x256x32, 8 warps, warp tile 64x64 ----------
#define BM 128
#define BN 256
#define BK 32
#define STAGES 4
#define NTHR 256

// dynamic smem layout (bytes)
#define SM_A    0                       // STAGES x 128x32 fp16 = 4 x 8192
#define SM_B    (STAGES * 8192)         // STAGES x 32x256 fp16 = 4 x 16384
#define SM_BIAS (SM_B + STAGES * 16384) // 98304 ; 256 fp32
#define SMEM_BYTES (SM_BIAS + 1024)     // 99328  (1 CTA/SM)

// ---------------- scratch (device globals; no allocations) -------------------
__device__ __align__(128) __half g_xh[(size_t)NTOK * HD];
__device__ __align__(128) __half g_w1h[(size_t)NE * HD * FD];
__device__ __align__(128) __half g_w2h[(size_t)NE * FD * HD];
__device__ __align__(128) __half g_h[(size_t)NSLOTP * FD];
__device__ float  g_y[(size_t)NSLOTP * HD];
__device__ int    g_tok_of_slot[NSLOTP];
__device__ int    g_slot_of_tok[NSLOT];
__device__ int    g_expert_of_tok[NSLOT];
__device__ float  g_gate_of_tok[NSLOT];
__device__ int    g_counts[NE];

// ---------------- helpers ----------------------------------------------------
__device__ __forceinline__ uint32_t smem_u32(const void* p) {
    uint32_t a;
    asm("{ .reg .u64 t; cvta.to.shared.u64 t, %1; cvt.u32.u64 %0, t; }" : "=r"(a) : "l"(p));
    return a;
}

__device__ __forceinline__ void cp16(uint32_t dst, const void* src) {
    asm volatile("cp.async.cg.shared.global [%0], [%1], 16;" :: "r"(dst), "l"(src));
}
__device__ __forceinline__ void cp_commit() {
    asm volatile("cp.async.commit_group;" ::: "memory");
}
__device__ __forceinline__ void cp_wait2() {
    asm volatile("cp.async.wait_group 2;" ::: "memory");
}

__device__ __forceinline__ void ldsm4(uint32_t r[4], uint32_t addr) {
    asm volatile("ldmatrix.sync.aligned.m8n8.x4.shared.b16 {%0,%1,%2,%3}, [%4];"
                 : "=r"(r[0]), "=r"(r[1]), "=r"(r[2]), "=r"(r[3]) : "r"(addr));
}
__device__ __forceinline__ void ldsm4t(uint32_t r[4], uint32_t addr) {
    asm volatile("ldmatrix.sync.aligned.m8n8.x4.trans.shared.b16 {%0,%1,%2,%3}, [%4];"
                 : "=r"(r[0]), "=r"(r[1]), "=r"(r[2]), "=r"(r[3]) : "r"(addr));
}

__device__ __forceinline__ void mma16816(float c[4], const uint32_t a[4],
                                         uint32_t b0, uint32_t b1) {
    asm volatile(
        "mma.sync.aligned.m16n8k16.row.col.f32.f16.f16.f32 "
        "{%0,%1,%2,%3}, {%4,%5,%6,%7}, {%8,%9}, {%0,%1,%2,%3};\n"
        : "+f"(c[0]), "+f"(c[1]), "+f"(c[2]), "+f"(c[3])
        : "r"(a[0]), "r"(a[1]), "r"(a[2]), "r"(a[3]), "r"(b0), "r"(b1));
}

__device__ __forceinline__ float gelu_exact(float x) {
    return 0.5f * x * (1.0f + erff(x * 0.70710678118654752440f));
}

// ---------------- stage 1: weight fp16 pre-convert (+zero counts) ------------
__global__ void cvt_kernel(const float* __restrict__ W1,
                           const float* __restrict__ W2) {
    if (blockIdx.x == 0 && blockIdx.y == 0 && threadIdx.x < NE)
        g_counts[threadIdx.x] = 0;
    const float* src = blockIdx.y ? W2 : W1;
    __half* dst = blockIdx.y ? g_w2h : g_w1h;
    const size_t n4 = (size_t)NE * HD * FD / 4;
    const size_t stride = (size_t)gridDim.x * blockDim.x;
    for (size_t i = blockIdx.x * blockDim.x + threadIdx.x; i < n4; i += stride) {
        float4 v = ((const float4*)src)[i];
        __half2 h0 = __floats2half2_rn(v.x, v.y);
        __half2 h1 = __floats2half2_rn(v.z, v.w);
        uint2 u = make_uint2(*(uint32_t*)&h0, *(uint32_t*)&h1);
        ((uint2*)dst)[i] = u;
    }
}

// ---------------- stage 2: router (+ x fp16 convert) -------------------------
__global__ void router_kernel(const float* __restrict__ x,
                              const float* __restrict__ Wr) {
    const int t = blockIdx.x;
    __shared__ float sx[HD];
    __shared__ float slog[NE];

    const float* xr = x + (size_t)t * HD;
    for (int i = threadIdx.x; i < HD; i += blockDim.x) {
        const float v = xr[i];
        sx[i] = v;
        g_xh[(size_t)t * HD + i] = __float2half_rn(v);
    }
    __syncthreads();

    const int w = threadIdx.x >> 5, lane = threadIdx.x & 31;
    if (w < NE) {
        const float* wr = Wr + (size_t)w * HD;
        float s = 0.f;
        for (int i = lane; i < HD; i += 32) s += sx[i] * wr[i];
        #pragma unroll
        for (int o = 16; o > 0; o >>= 1) s += __shfl_xor_sync(0xffffffffu, s, o);
        if (lane == 0) slog[w] = s;
    }
    __syncthreads();

    if (threadIdx.x == 0) {
        int i0 = 0; float v0 = slog[0];
        #pragma unroll
        for (int e = 1; e < NE; e++) if (slog[e] > v0) { v0 = slog[e]; i0 = e; }
        int i1 = -1; float v1 = -INFINITY;
        #pragma unroll
        for (int e = 0; e < NE; e++) {
            if (e == i0) continue;
            if (slog[e] > v1) { v1 = slog[e]; i1 = e; }
        }
        float e1 = expf(v1 - v0);
        float inv = 1.f / (1.f + e1);
        g_expert_of_tok[t * 2 + 0] = i0; g_gate_of_tok[t * 2 + 0] = inv;
        g_expert_of_tok[t * 2 + 1] = i1; g_gate_of_tok[t * 2 + 1] = e1 * inv;
        atomicAdd(&g_counts[i0], 1);
        atomicAdd(&g_counts[i1], 1);
    }
}

// ---------------- stage 3: compaction into 128-padded ranges -----------------
__global__ void build_kernel() {
    const int e = blockIdx.x;
    __shared__ int warp_sums[32];
    int base = 0;
    #pragma unroll
    for (int i = 0; i < NE; i++)
        if (i < e) base += ((g_counts[i] + 127) >> 7) << 7;
    const int lane = threadIdx.x & 31, w = threadIdx.x >> 5;

    for (int t0 = 0; t0 < NTOK; t0 += 1024) {
        const int t = t0 + threadIdx.x;
        int k = -1;
        if (g_expert_of_tok[t * 2 + 0] == e) k = 0;
        else if (g_expert_of_tok[t * 2 + 1] == e) k = 1;
        const int flag = (k >= 0) ? 1 : 0;

        const unsigned bal = __ballot_sync(0xffffffffu, flag);
        const int pre = __popc(bal & ((1u << lane) - 1u));
        if (lane == 0) warp_sums[w] = __popc(bal);
        __syncthreads();
        int woff = 0, total = 0;
        #pragma unroll
        for (int i = 0; i < 32; i++) {
            if (i < w) woff += warp_sums[i];
            total += warp_sums[i];
        }
        if (flag) {
            const int slot = base + woff + pre;
            g_tok_of_slot[slot] = t;
            g_slot_of_tok[t * 2 + k] = slot;
        }
        base += total;
        __syncthreads();
    }
}

// ---------------- stage 4/5: routed fp16 GEMM, k-tile-wide fragment DB -------
// FIRST=true : g_h(fp16) = gelu(g_xh[gather] @ W1h[e] + b1[e])   K=HD,  N=FD
// FIRST=false: g_y(fp32) = g_h[padded] @ W2h[e]                  K=FD,  N=HD
template <bool FIRST>
__global__ __launch_bounds__(NTHR, 1) void moe_mma(const float* __restrict__ bias) {
    constexpr int KDIM = FIRST ? HD : FD;
    constexpr int NDIM = FIRST ? FD : HD;
    constexpr int NKT  = KDIM / BK;

    // ---- flattened m-tile decode: blockIdx.y -> (expert, m0, padded off) ----
    const int j = blockIdx.y;
    int e = -1, m0 = 0, off = 0, ne = 0;
    {
        int cum = 0, poff = 0;
        #pragma unroll
        for (int i = 0; i < NE; i++) {
            const int c  = g_counts[i];
            const int mt = (c + BM - 1) >> 7;
            if (e < 0 && j < cum + mt) { e = i; m0 = (j - cum) << 7; off = poff; ne = c; }
            cum  += mt;
            poff += mt << 7;
        }
    }
    if (e < 0) return;
    const int n0 = blockIdx.x * BN;

    extern __shared__ char smem[];
    const uint32_t sb = smem_u32(smem);
    const int tid = threadIdx.x;

    if (FIRST && tid < 64)
        ((float4*)(smem + SM_BIAS))[tid] =
            ((const float4*)(bias + (size_t)e * NDIM + n0))[tid];

    const __half* Ab = FIRST ? g_xh : g_h;
    const __half* Wb = (FIRST ? g_w1h : g_w2h) + (size_t)e * KDIM * NDIM;

    // ---- cp.async staging maps ----
    // A: thread -> row r = tid>>1, 32B chunk hs = tid&1 (granules hs*2, hs*2+1)
    const int r = tid >> 1, hs = tid & 1;
    int ga = m0 + r; if (ga > ne - 1) ga = ne - 1;
    const int rowid = FIRST ? g_tok_of_slot[off + ga] : (off + ga);
    const __half* asrc = Ab + (size_t)rowid * KDIM + hs * 16;
    const uint32_t ad0 = (uint32_t)(r * 64 + (((hs * 2 + 0) ^ ((r >> 1) & 3)) * 16));
    const uint32_t ad1 = (uint32_t)(r * 64 + (((hs * 2 + 1) ^ ((r >> 1) & 3)) * 16));

    // B: thread -> k-row kk = tid>>3, lane8 = tid&7, granules lane8 + 8j
    const int kk = tid >> 3, lane8 = tid & 7;
    const __half* bsrc = Wb + (size_t)kk * NDIM + n0 + lane8 * 8;
    uint32_t bd[4];
    #pragma unroll
    for (int jj = 0; jj < 4; jj++)
        bd[jj] = (uint32_t)(kk * 512 + (((lane8 + 8 * jj) ^ (kk & 7)) * 16));

    // ---- ldmatrix fragment maps: warp grid 2(M) x 4(N), warp tile 64x64 ----
    const int w = tid >> 5, lane = tid & 31;
    const int wm = w & 1, wn = w >> 1;
    const int l16 = lane & 15, lh = lane >> 4;
    uint32_t ao[2][4], bo[2][4];
    #pragma unroll
    for (int ks = 0; ks < 2; ks++) {
        #pragma unroll
        for (int mi = 0; mi < 4; mi++) {
            const int row = wm * 64 + mi * 16 + l16;
            const int gr  = ks * 2 + lh;
            ao[ks][mi] = (uint32_t)(row * 64 + ((gr ^ ((row >> 1) & 3)) * 16));
        }
        #pragma unroll
        for (int np = 0; np < 4; np++) {
            const int kr = ks * 16 + l16;
            const int ng = wn * 8 + np * 2 + lh;
            bo[ks][np] = (uint32_t)(kr * 512 + ((ng ^ (kr & 7)) * 16));
        }
    }

    float acc[4][8][4];
    #pragma unroll
    for (int mi = 0; mi < 4; mi++)
        #pragma unroll
        for (int ni = 0; ni < 8; ni++)
            #pragma unroll
            for (int q = 0; q < 4; q++) acc[mi][ni][q] = 0.f;

    auto issue_stage = [&](int kt) {
        const uint32_t sa  = sb + SM_A + (kt & (STAGES - 1)) * 8192;
        const uint32_t sbm = sb + SM_B + (kt & (STAGES - 1)) * 16384;
        const __half* ap = asrc + (size_t)kt * BK;
        cp16(sa + ad0, ap);
        cp16(sa + ad1, ap + 8);
        const __half* bp = bsrc + (size_t)kt * BK * NDIM;
        #pragma unroll
        for (int jj = 0; jj < 4; jj++) cp16(sbm + bd[jj], bp + 64 * jj);
    };

    // ---- prologue: fill 3 stages ----
    #pragma unroll
    for (int s = 0; s < STAGES - 1; s++) { issue_stage(s); cp_commit(); }

    // ---- mainloop: all 16 ldsm up front, then 64 mma stream ------------------
    #pragma unroll 1
    for (int kt = 0; kt < NKT; kt++) {
        cp_wait2();
        __syncthreads();

        if (kt + STAGES - 1 < NKT) issue_stage(kt + STAGES - 1);
        cp_commit();

        const int buf = kt & (STAGES - 1);
        const uint32_t sA = sb + SM_A + buf * 8192;
        const uint32_t sB = sb + SM_B + buf * 16384;

        uint32_t af[2][4][4], bf[2][4][4];
        #pragma unroll
        for (int ks = 0; ks < 2; ks++) {
            #pragma unroll
            for (int mi = 0; mi < 4; mi++) ldsm4(af[ks][mi], sA + ao[ks][mi]);
            #pragma unroll
            for (int np = 0; np < 4; np++) ldsm4t(bf[ks][np], sB + bo[ks][np]);
        }
        #pragma unroll
        for (int ks = 0; ks < 2; ks++) {
            #pragma unroll
            for (int np = 0; np < 4; np++) {
                #pragma unroll
                for (int mi = 0; mi < 4; mi++) {
                    mma16816(acc[mi][np * 2 + 0], af[ks][mi], bf[ks][np][0], bf[ks][np][1]);
                    mma16816(acc[mi][np * 2 + 1], af[ks][mi], bf[ks][np][2], bf[ks][np][3]);
                }
            }
        }
    }

    // ---- epilogue ----
    const int rbase = wm * 64 + (lane >> 2);
    const int cbase = wn * 64 + (lane & 3) * 2;
    #pragma unroll
    for (int mi = 0; mi < 4; mi++) {
        #pragma unroll
        for (int hrow = 0; hrow < 2; hrow++) {
            const int mloc = rbase + mi * 16 + hrow * 8;
            const int grow = m0 + mloc;
            if (grow >= ne) continue;
            #pragma unroll
            for (int ni = 0; ni < 8; ni++) {
                const int cr = cbase + ni * 8;
                float v0 = acc[mi][ni][hrow * 2 + 0];
                float v1 = acc[mi][ni][hrow * 2 + 1];
                if (FIRST) {
                    const float2 bv = *(const float2*)(smem + SM_BIAS + cr * 4);
                    v0 = gelu_exact(v0 + bv.x);
                    v1 = gelu_exact(v1 + bv.y);
                    __half2 hv = __floats2half2_rn(v0, v1);
                    *(__half2*)(g_h + (size_t)(off + grow) * NDIM + n0 + cr) = hv;
                } else {
                    *(float2*)(g_y + (size_t)(off + grow) * NDIM + n0 + cr) =
                        make_float2(v0, v1);
                }
            }
        }
    }
}

// ---------------- stage 6: gated combine -------------------------------------
__global__ void combine_kernel(const float* __restrict__ b2,
                               float* __restrict__ out) {
    const int t  = blockIdx.x;
    const int e0 = g_expert_of_tok[t * 2 + 0], e1 = g_expert_of_tok[t * 2 + 1];
    const float gg0 = g_gate_of_tok[t * 2 + 0], gg1 = g_gate_of_tok[t * 2 + 1];
    const int s0 = g_slot_of_tok[t * 2 + 0], s1 = g_slot_of_tok[t * 2 + 1];

    const float4* y0  = (const float4*)(g_y + (size_t)s0 * HD);
    const float4* y1  = (const float4*)(g_y + (size_t)s1 * HD);
    const float4* bb0 = (const float4*)(b2 + (size_t)e0 * HD);
    const float4* bb1 = (const float4*)(b2 + (size_t)e1 * HD);
    float4* o = (float4*)(out + (size_t)t * HD);

    for (int i = threadIdx.x; i < HD / 4; i += blockDim.x) {
        const float4 a = y0[i], b = y1[i], c = bb0[i], d = bb1[i];
        float4 rr;
        rr.x = gg0 * (a.x + c.x) + gg1 * (b.x + d.x);
        rr.y = gg0 * (a.y + c.y) + gg1 * (b.y + d.y);
        rr.z = gg0 * (a.z + c.z) + gg1 * (b.z + d.z);
        rr.w = gg0 * (a.w + c.w) + gg1 * (b.w + d.w);
        o[i] = rr;
    }
}

// ---------------- launch ------------------------------------------------------
extern "C" void kernel_launch(void* const* d_in, const int* in_sizes, int n_in,
                              void* d_out, int out_size) {
    const float* x  = (const float*)d_in[0];
    const float* Wr = (const float*)d_in[1];
    const float* W1 = (const float*)d_in[2];
    const float* b1 = (const float*)d_in[3];
    const float* W2 = (const float*)d_in[4];
    const float* b2 = (const float*)d_in[5];
    float* out = (float*)d_out;

    cudaFuncSetAttribute(moe_mma<true>,  cudaFuncAttributeMaxDynamicSharedMemorySize, SMEM_BYTES);
    cudaFuncSetAttribute(moe_mma<false>, cudaFuncAttributeMaxDynamicSharedMemorySize, SMEM_BYTES);

    cvt_kernel<<<dim3(1024, 2), 256>>>(W1, W2);
    router_kernel<<<NTOK, 256>>>(x, Wr);
    build_kernel<<<NE, 1024>>>();
    moe_mma<true><<<dim3(FD / BN, MAXMT), NTHR, SMEM_BYTES>>>(b1);
    moe_mma<false><<<dim3(HD / BN, MAXMT), NTHR, SMEM_BYTES>>>(nullptr);
    combine_kernel<<<NTOK, 256>>>(b2, out);
}

// round 12
// speedup vs baseline: 1.2691x; 1.2691x over previous
#include <cuda_runtime.h>
#include <cuda_fp16.h>
#include <math.h>
#include <stdint.h>

// ---------------- problem constants -----------------------------------------
#define NTOK 4096
#define HD   1024
#define NE   8
#define FD   4096
#define NSLOT (NTOK * 2)
#define NSLOTP (NSLOT + NE * 128)      // 128-padded per-expert ranges
#define MAXMT 71                        // max total m-tiles (64 + 7 pad)

// ---------------- GEMM tiling (R10 best: 128x128x32, 2 CTAs/SM) --------------
#define BM 128
#define BN 128
#define BK 32
#define STAGES 4
#define NTHR 256

// dynamic smem layout (bytes); stage = A 8KB + B 8KB
#define SM_A    0                       // STAGES x 128x32 fp16
#define SM_B    (STAGES * 8192)         // STAGES x 32x128 fp16
#define SM_BIAS (SM_B + STAGES * 8192)  // 65536 ; 128 fp32
#define SMEM_BYTES (SM_BIAS + 512)      // 66048  (2 CTAs/SM -> 132KB)

// ---------------- scratch (device globals; no allocations) -------------------
__device__ __align__(128) __half g_xh[(size_t)NTOK * HD];
__device__ __align__(128) __half g_w1h[(size_t)NE * HD * FD];
__device__ __align__(128) __half g_w2h[(size_t)NE * FD * HD];
__device__ __align__(128) __half g_h[(size_t)NSLOTP * FD];
__device__ float  g_y[(size_t)NSLOTP * HD];
__device__ int    g_tok_of_slot[NSLOTP];
__device__ int    g_slot_of_tok[NSLOT];
__device__ int    g_expert_of_tok[NSLOT];
__device__ float  g_gate_of_tok[NSLOT];
__device__ int    g_counts[NE];

// ---------------- helpers ----------------------------------------------------
__device__ __forceinline__ uint32_t smem_u32(const void* p) {
    uint32_t a;
    asm("{ .reg .u64 t; cvta.to.shared.u64 t, %1; cvt.u32.u64 %0, t; }" : "=r"(a) : "l"(p));
    return a;
}

__device__ __forceinline__ void cp16(uint32_t dst, const void* src) {
    asm volatile("cp.async.cg.shared.global [%0], [%1], 16;" :: "r"(dst), "l"(src));
}
__device__ __forceinline__ void cp_commit() {
    asm volatile("cp.async.commit_group;" ::: "memory");
}
__device__ __forceinline__ void cp_wait2() {
    asm volatile("cp.async.wait_group 2;" ::: "memory");
}

__device__ __forceinline__ void ldsm4(uint32_t r[4], uint32_t addr) {
    asm volatile("ldmatrix.sync.aligned.m8n8.x4.shared.b16 {%0,%1,%2,%3}, [%4];"
                 : "=r"(r[0]), "=r"(r[1]), "=r"(r[2]), "=r"(r[3]) : "r"(addr));
}
__device__ __forceinline__ void ldsm4t(uint32_t r[4], uint32_t addr) {
    asm volatile("ldmatrix.sync.aligned.m8n8.x4.trans.shared.b16 {%0,%1,%2,%3}, [%4];"
                 : "=r"(r[0]), "=r"(r[1]), "=r"(r[2]), "=r"(r[3]) : "r"(addr));
}

__device__ __forceinline__ void mma16816(float c[4], const uint32_t a[4],
                                         uint32_t b0, uint32_t b1) {
    asm volatile(
        "mma.sync.aligned.m16n8k16.row.col.f32.f16.f16.f32 "
        "{%0,%1,%2,%3}, {%4,%5,%6,%7}, {%8,%9}, {%0,%1,%2,%3};\n"
        : "+f"(c[0]), "+f"(c[1]), "+f"(c[2]), "+f"(c[3])
        : "r"(a[0]), "r"(a[1]), "r"(a[2]), "r"(a[3]), "r"(b0), "r"(b1));
}

__device__ __forceinline__ float gelu_exact(float x) {
    return 0.5f * x * (1.0f + erff(x * 0.70710678118654752440f));
}

// ---------------- counts init (before stream fork) ----------------------------
__global__ void init_kernel() {
    if (threadIdx.x < NE) g_counts[threadIdx.x] = 0;
}

// ---------------- weight fp16 pre-convert (one matrix per launch) -------------
__global__ void cvt_w_kernel(const float* __restrict__ src, int which) {
    __half* dst = which ? g_w2h : g_w1h;
    const size_t n4 = (size_t)NE * HD * FD / 4;
    const size_t stride = (size_t)gridDim.x * blockDim.x;
    for (size_t i = blockIdx.x * blockDim.x + threadIdx.x; i < n4; i += stride) {
        float4 v = ((const float4*)src)[i];
        __half2 h0 = __floats2half2_rn(v.x, v.y);
        __half2 h1 = __floats2half2_rn(v.z, v.w);
        uint2 u = make_uint2(*(uint32_t*)&h0, *(uint32_t*)&h1);
        ((uint2*)dst)[i] = u;
    }
}

// ---------------- router (+ x fp16 convert) -----------------------------------
__global__ void router_kernel(const float* __restrict__ x,
                              const float* __restrict__ Wr) {
    const int t = blockIdx.x;
    __shared__ float sx[HD];
    __shared__ float slog[NE];

    const float* xr = x + (size_t)t * HD;
    for (int i = threadIdx.x; i < HD; i += blockDim.x) {
        const float v = xr[i];
        sx[i] = v;
        g_xh[(size_t)t * HD + i] = __float2half_rn(v);
    }
    __syncthreads();

    const int w = threadIdx.x >> 5, lane = threadIdx.x & 31;
    if (w < NE) {
        const float* wr = Wr + (size_t)w * HD;
        float s = 0.f;
        for (int i = lane; i < HD; i += 32) s += sx[i] * wr[i];
        #pragma unroll
        for (int o = 16; o > 0; o >>= 1) s += __shfl_xor_sync(0xffffffffu, s, o);
        if (lane == 0) slog[w] = s;
    }
    __syncthreads();

    if (threadIdx.x == 0) {
        int i0 = 0; float v0 = slog[0];
        #pragma unroll
        for (int e = 1; e < NE; e++) if (slog[e] > v0) { v0 = slog[e]; i0 = e; }
        int i1 = -1; float v1 = -INFINITY;
        #pragma unroll
        for (int e = 0; e < NE; e++) {
            if (e == i0) continue;
            if (slog[e] > v1) { v1 = slog[e]; i1 = e; }
        }
        float e1 = expf(v1 - v0);
        float inv = 1.f / (1.f + e1);
        g_expert_of_tok[t * 2 + 0] = i0; g_gate_of_tok[t * 2 + 0] = inv;
        g_expert_of_tok[t * 2 + 1] = i1; g_gate_of_tok[t * 2 + 1] = e1 * inv;
        atomicAdd(&g_counts[i0], 1);
        atomicAdd(&g_counts[i1], 1);
    }
}

// ---------------- compaction into 128-padded ranges ---------------------------
__global__ void build_kernel() {
    const int e = blockIdx.x;
    __shared__ int warp_sums[32];
    int base = 0;
    #pragma unroll
    for (int i = 0; i < NE; i++)
        if (i < e) base += ((g_counts[i] + 127) >> 7) << 7;
    const int lane = threadIdx.x & 31, w = threadIdx.x >> 5;

    for (int t0 = 0; t0 < NTOK; t0 += 1024) {
        const int t = t0 + threadIdx.x;
        int k = -1;
        if (g_expert_of_tok[t * 2 + 0] == e) k = 0;
        else if (g_expert_of_tok[t * 2 + 1] == e) k = 1;
        const int flag = (k >= 0) ? 1 : 0;

        const unsigned bal = __ballot_sync(0xffffffffu, flag);
        const int pre = __popc(bal & ((1u << lane) - 1u));
        if (lane == 0) warp_sums[w] = __popc(bal);
        __syncthreads();
        int woff = 0, total = 0;
        #pragma unroll
        for (int i = 0; i < 32; i++) {
            if (i < w) woff += warp_sums[i];
            total += warp_sums[i];
        }
        if (flag) {
            const int slot = base + woff + pre;
            g_tok_of_slot[slot] = t;
            g_slot_of_tok[t * 2 + k] = slot;
        }
        base += total;
        __syncthreads();
    }
}

// ---------------- routed fp16 GEMM (R10 verbatim) -----------------------------
// FIRST=true : g_h(fp16) = gelu(g_xh[gather] @ W1h[e] + b1[e])   K=HD,  N=FD
// FIRST=false: g_y(fp32) = g_h[padded] @ W2h[e]                  K=FD,  N=HD
template <bool FIRST>
__global__ __launch_bounds__(NTHR, 2) void moe_mma(const float* __restrict__ bias) {
    constexpr int KDIM = FIRST ? HD : FD;
    constexpr int NDIM = FIRST ? FD : HD;
    constexpr int NKT  = KDIM / BK;

    // ---- flattened m-tile decode: blockIdx.y -> (expert, m0, padded off) ----
    const int j = blockIdx.y;
    int e = -1, m0 = 0, off = 0, ne = 0;
    {
        int cum = 0, poff = 0;
        #pragma unroll
        for (int i = 0; i < NE; i++) {
            const int c  = g_counts[i];
            const int mt = (c + BM - 1) >> 7;
            if (e < 0 && j < cum + mt) { e = i; m0 = (j - cum) << 7; off = poff; ne = c; }
            cum  += mt;
            poff += mt << 7;
        }
    }
    if (e < 0) return;
    const int n0 = blockIdx.x * BN;

    extern __shared__ char smem[];
    const uint32_t sb = smem_u32(smem);
    const int tid = threadIdx.x;

    if (FIRST && tid < 32)
        ((float4*)(smem + SM_BIAS))[tid] =
            ((const float4*)(bias + (size_t)e * NDIM + n0))[tid];

    const __half* Ab = FIRST ? g_xh : g_h;
    const __half* Wb = (FIRST ? g_w1h : g_w2h) + (size_t)e * KDIM * NDIM;

    // ---- cp.async staging maps ----
    const int r = tid >> 1, hs = tid & 1;
    int ga = m0 + r; if (ga > ne - 1) ga = ne - 1;
    const int rowid = FIRST ? g_tok_of_slot[off + ga] : (off + ga);
    const __half* asrc = Ab + (size_t)rowid * KDIM + hs * 16;
    const uint32_t ad0 = (uint32_t)(r * 64 + (((hs * 2 + 0) ^ ((r >> 1) & 3)) * 16));
    const uint32_t ad1 = (uint32_t)(r * 64 + (((hs * 2 + 1) ^ ((r >> 1) & 3)) * 16));

    const int kk = tid >> 3, lane8 = tid & 7;
    const __half* bsrc = Wb + (size_t)kk * NDIM + n0 + lane8 * 8;
    uint32_t bd[2];
    #pragma unroll
    for (int jj = 0; jj < 2; jj++)
        bd[jj] = (uint32_t)(kk * 256 + (((lane8 + 8 * jj) ^ (kk & 7)) * 16));

    // ---- ldmatrix fragment maps: warp grid 2(M) x 4(N), warp tile 64x32 ----
    const int w = tid >> 5, lane = tid & 31;
    const int wm = w & 1, wn = w >> 1;
    const int l16 = lane & 15, lh = lane >> 4;
    uint32_t ao[2][4], bo[2][2];
    #pragma unroll
    for (int ks = 0; ks < 2; ks++) {
        #pragma unroll
        for (int mi = 0; mi < 4; mi++) {
            const int row = wm * 64 + mi * 16 + l16;
            const int gr  = ks * 2 + lh;
            ao[ks][mi] = (uint32_t)(row * 64 + ((gr ^ ((row >> 1) & 3)) * 16));
        }
        #pragma unroll
        for (int nb = 0; nb < 2; nb++) {
            const int kr = ks * 16 + l16;
            const int ng = wn * 4 + nb * 2 + lh;
            bo[ks][nb] = (uint32_t)(kr * 256 + ((ng ^ (kr & 7)) * 16));
        }
    }

    float acc[4][4][4];
    #pragma unroll
    for (int mi = 0; mi < 4; mi++)
        #pragma unroll
        for (int ni = 0; ni < 4; ni++)
            #pragma unroll
            for (int q = 0; q < 4; q++) acc[mi][ni][q] = 0.f;

    auto issue_stage = [&](int kt) {
        const uint32_t sa  = sb + SM_A + (kt & (STAGES - 1)) * 8192;
        const uint32_t sbm = sb + SM_B + (kt & (STAGES - 1)) * 8192;
        const __half* ap = asrc + (size_t)kt * BK;
        cp16(sa + ad0, ap);
        cp16(sa + ad1, ap + 8);
        const __half* bp = bsrc + (size_t)kt * BK * NDIM;
        cp16(sbm + bd[0], bp);
        cp16(sbm + bd[1], bp + 64);
    };

    // ---- prologue: fill 3 stages ----
    #pragma unroll
    for (int s = 0; s < STAGES - 1; s++) { issue_stage(s); cp_commit(); }

    // ---- phase skew (kept from R10) ----
    {
        const int lbid = blockIdx.x + gridDim.x * blockIdx.y;
        if ((lbid / 148) & 1) {
            const long long t0 = clock64();
            while (clock64() - t0 < 480) {}
        }
    }

    // ---- mainloop ----
    #pragma unroll 1
    for (int kt = 0; kt < NKT; kt++) {
        cp_wait2();
        __syncthreads();

        const int buf = kt & (STAGES - 1);
        const uint32_t sA = sb + SM_A + buf * 8192;
        const uint32_t sB = sb + SM_B + buf * 8192;
        #pragma unroll
        for (int ks = 0; ks < 2; ks++) {
            uint32_t af[4][4], bf[2][4];
            ldsm4 (af[0], sA + ao[ks][0]);
            ldsm4 (af[1], sA + ao[ks][1]);
            ldsm4 (af[2], sA + ao[ks][2]);
            ldsm4 (af[3], sA + ao[ks][3]);
            ldsm4t(bf[0], sB + bo[ks][0]);
            ldsm4t(bf[1], sB + bo[ks][1]);
            #pragma unroll
            for (int nb = 0; nb < 2; nb++) {
                #pragma unroll
                for (int mi = 0; mi < 4; mi++) {
                    mma16816(acc[mi][nb * 2 + 0], af[mi], bf[nb][0], bf[nb][1]);
                    mma16816(acc[mi][nb * 2 + 1], af[mi], bf[nb][2], bf[nb][3]);
                }
            }
        }

        if (kt + STAGES - 1 < NKT) issue_stage(kt + STAGES - 1);
        cp_commit();
    }

    // ---- epilogue ----
    const int rbase = wm * 64 + (lane >> 2);
    const int cbase = wn * 32 + (lane & 3) * 2;
    #pragma unroll
    for (int mi = 0; mi < 4; mi++) {
        #pragma unroll
        for (int hrow = 0; hrow < 2; hrow++) {
            const int mloc = rbase + mi * 16 + hrow * 8;
            const int grow = m0 + mloc;
            if (grow >= ne) continue;
            #pragma unroll
            for (int ni = 0; ni < 4; ni++) {
                const int cr = cbase + ni * 8;
                float v0 = acc[mi][ni][hrow * 2 + 0];
                float v1 = acc[mi][ni][hrow * 2 + 1];
                if (FIRST) {
                    const float2 bv = *(const float2*)(smem + SM_BIAS + cr * 4);
                    v0 = gelu_exact(v0 + bv.x);
                    v1 = gelu_exact(v1 + bv.y);
                    __half2 hv = __floats2half2_rn(v0, v1);
                    *(__half2*)(g_h + (size_t)(off + grow) * NDIM + n0 + cr) = hv;
                } else {
                    *(float2*)(g_y + (size_t)(off + grow) * NDIM + n0 + cr) =
                        make_float2(v0, v1);
                }
            }
        }
    }
}

// ---------------- gated combine -----------------------------------------------
__global__ void combine_kernel(const float* __restrict__ b2,
                               float* __restrict__ out) {
    const int t  = blockIdx.x;
    const int e0 = g_expert_of_tok[t * 2 + 0], e1 = g_expert_of_tok[t * 2 + 1];
    const float gg0 = g_gate_of_tok[t * 2 + 0], gg1 = g_gate_of_tok[t * 2 + 1];
    const int s0 = g_slot_of_tok[t * 2 + 0], s1 = g_slot_of_tok[t * 2 + 1];

    const float4* y0  = (const float4*)(g_y + (size_t)s0 * HD);
    const float4* y1  = (const float4*)(g_y + (size_t)s1 * HD);
    const float4* bb0 = (const float4*)(b2 + (size_t)e0 * HD);
    const float4* bb1 = (const float4*)(b2 + (size_t)e1 * HD);
    float4* o = (float4*)(out + (size_t)t * HD);

    for (int i = threadIdx.x; i < HD / 4; i += blockDim.x) {
        const float4 a = y0[i], b = y1[i], c = bb0[i], d = bb1[i];
        float4 rr;
        rr.x = gg0 * (a.x + c.x) + gg1 * (b.x + d.x);
        rr.y = gg0 * (a.y + c.y) + gg1 * (b.y + d.y);
        rr.z = gg0 * (a.z + c.z) + gg1 * (b.z + d.z);
        rr.w = gg0 * (a.w + c.w) + gg1 * (b.w + d.w);
        o[i] = rr;
    }
}

// ---------------- launch: forked-stream capture graph -------------------------
extern "C" void kernel_launch(void* const* d_in, const int* in_sizes, int n_in,
                              void* d_out, int out_size) {
    const float* x  = (const float*)d_in[0];
    const float* Wr = (const float*)d_in[1];
    const float* W1 = (const float*)d_in[2];
    const float* b1 = (const float*)d_in[3];
    const float* W2 = (const float*)d_in[4];
    const float* b2 = (const float*)d_in[5];
    float* out = (float*)d_out;

    static cudaStream_t s1 = nullptr, s2 = nullptr, s3 = nullptr;
    static cudaEvent_t  e0 = nullptr, e1 = nullptr, e2 = nullptr, e3 = nullptr;
    if (s1 == nullptr) {
        cudaStreamCreateWithFlags(&s1, cudaStreamNonBlocking);
        cudaStreamCreateWithFlags(&s2, cudaStreamNonBlocking);
        cudaStreamCreateWithFlags(&s3, cudaStreamNonBlocking);
        cudaEventCreateWithFlags(&e0, cudaEventDisableTiming);
        cudaEventCreateWithFlags(&e1, cudaEventDisableTiming);
        cudaEventCreateWithFlags(&e2, cudaEventDisableTiming);
        cudaEventCreateWithFlags(&e3, cudaEventDisableTiming);
    }

    cudaFuncSetAttribute(moe_mma<true>,  cudaFuncAttributeMaxDynamicSharedMemorySize, SMEM_BYTES);
    cudaFuncSetAttribute(moe_mma<false>, cudaFuncAttributeMaxDynamicSharedMemorySize, SMEM_BYTES);

    // serial prefix: zero counts, then fork
    init_kernel<<<1, 32>>>();
    cudaEventRecord(e0, 0);

    // s1: router -> build
    cudaStreamWaitEvent(s1, e0, 0);
    router_kernel<<<NTOK, 256, 0, s1>>>(x, Wr);
    build_kernel<<<NE, 1024, 0, s1>>>();
    cudaEventRecord(e1, s1);

    // s2: cvt W1 ; s3: cvt W2
    cudaStreamWaitEvent(s2, e0, 0);
    cvt_w_kernel<<<1024, 256, 0, s2>>>(W1, 0);
    cudaEventRecord(e2, s2);
    cudaStreamWaitEvent(s3, e0, 0);
    cvt_w_kernel<<<1024, 256, 0, s3>>>(W2, 1);
    cudaEventRecord(e3, s3);

    // GEMM1 needs router/build + W1h ; cvt W2 overlaps GEMM1
    cudaStreamWaitEvent(0, e1, 0);
    cudaStreamWaitEvent(0, e2, 0);
    moe_mma<true><<<dim3(FD / BN, MAXMT), NTHR, SMEM_BYTES>>>(b1);

    // GEMM2 additionally needs W2h
    cudaStreamWaitEvent(0, e3, 0);
    moe_mma<false><<<dim3(HD / BN, MAXMT), NTHR, SMEM_BYTES>>>(nullptr);

    combine_kernel<<<NTOK, 256>>>(b2, out);
}